// round 1
// baseline (speedup 1.0000x reference)
#include <cuda_runtime.h>
#include <math.h>

// Problem constants
#define NC   22            // columns
#define NE   12            // embeddings per column
#define DD   64            // feature dim
#define BB   2048          // batch
#define NPAIR 231          // 22 choose 2
#define NENT  253          // 22 lin/diag entries + 231 pair entries (float4 each)

// ---------------- device scratch (static allocation is allowed) ----------------
__device__ float g_sp[NC * NE * DD];            // 0.01 * softplus(emb_std)
__device__ float g_wpack[DD * NENT * 4];        // per-d packed float4 weights
__device__ float g_e[NC * DD * BB];             // e[i][d][b]
__device__ float g_partial[DD * BB * 2];        // partial[d][b*2+k]

// ---------------- stage 0a: softplus table --------------------------------------
__global__ void prep_sp(const float* __restrict__ emb_std) {
    int t = blockIdx.x * 256 + threadIdx.x;
    if (t < NC * NE * DD) {
        float x = emb_std[t];
        // jax.nn.softplus = logaddexp(x, 0) = max(x,0) + log1p(exp(-|x|))
        float sp = fmaxf(x, 0.0f) + log1pf(expf(-fabsf(x)));
        g_sp[t] = 0.01f * sp;
    }
}

// ---------------- stage 0b: combined weights ------------------------------------
// Packed layout per d (contiguous 253 float4):
//   entry 0..21  : {L0, L1, w1*Wmul[i][i][d][0], w1*Wmul[i][i][d][1]}
//   entry 22..252: {wm0, wm1, wa0, wa1} for strict-upper pair p
__global__ void prep_weights(const float* __restrict__ W_ops,
                             const float* __restrict__ W_cat,
                             const float* __restrict__ log_alpha) {
    int d = threadIdx.x;                                  // 0..63
    int entry = blockIdx.x * blockDim.y + threadIdx.y;    // 0..255
    if (entry >= NENT) return;

    // softmax over 5 primitives (redundant per-thread, trivial)
    float la[5], w[5];
    float mx = -1e30f, s = 0.f;
    #pragma unroll
    for (int z = 0; z < 5; z++) { la[z] = log_alpha[z]; mx = fmaxf(mx, la[z]); }
    #pragma unroll
    for (int z = 0; z < 5; z++) { w[z] = expf(la[z] - mx); s += w[z]; }
    #pragma unroll
    for (int z = 0; z < 5; z++) w[z] /= s;
    float w0 = w[0], w1 = w[1], w2 = w[2], w3 = w[3], w4 = w[4];

    float4 r;
    if (entry < NC) {
        int i = entry;
        float l0 = 0.f, l1 = 0.f;
        for (int j = 0; j < NC; j++) {
            const float* Pij = W_ops + (((i*NC+j)*4 + 0)*DD + d)*2;
            const float* Pji = W_ops + (((j*NC+i)*4 + 0)*DD + d)*2;
            const float* Xij = W_ops + (((i*NC+j)*4 + 2)*DD + d)*2;
            const float* Xji = W_ops + (((j*NC+i)*4 + 2)*DD + d)*2;
            const float* Nij = W_ops + (((i*NC+j)*4 + 3)*DD + d)*2;
            const float* Nji = W_ops + (((j*NC+i)*4 + 3)*DD + d)*2;
            const float* Cij  = W_cat + ((i*NC+j)*2*DD + d)*2;        // r = d
            const float* Cjiq = W_cat + ((j*NC+i)*2*DD + DD + d)*2;   // r = 64+d
            l0 += w0*(Pij[0]+Pji[0]) + 0.5f*w2*(Xij[0]+Xji[0])
                + 0.5f*w3*(Nij[0]+Nji[0]) + w4*(Cij[0]+Cjiq[0]);
            l1 += w0*(Pij[1]+Pji[1]) + 0.5f*w2*(Xij[1]+Xji[1])
                + 0.5f*w3*(Nij[1]+Nji[1]) + w4*(Cij[1]+Cjiq[1]);
        }
        const float* Mii = W_ops + (((i*NC+i)*4 + 1)*DD + d)*2;
        r.x = l0; r.y = l1; r.z = w1*Mii[0]; r.w = w1*Mii[1];
    } else {
        int p = entry - NC;
        int i = 0, rem = p;
        while (rem >= 21 - i) { rem -= 21 - i; i++; }
        int j = i + 1 + rem;
        const float* Mij = W_ops + (((i*NC+j)*4 + 1)*DD + d)*2;
        const float* Mji = W_ops + (((j*NC+i)*4 + 1)*DD + d)*2;
        const float* Xij = W_ops + (((i*NC+j)*4 + 2)*DD + d)*2;
        const float* Xji = W_ops + (((j*NC+i)*4 + 2)*DD + d)*2;
        const float* Nij = W_ops + (((i*NC+j)*4 + 3)*DD + d)*2;
        const float* Nji = W_ops + (((j*NC+i)*4 + 3)*DD + d)*2;
        r.x = w1*(Mij[0]+Mji[0]);
        r.y = w1*(Mij[1]+Mji[1]);
        r.z = 0.5f*(w2*(Xij[0]+Xji[0]) - w3*(Nij[0]+Nji[0]));
        r.w = 0.5f*(w2*(Xij[1]+Xji[1]) - w3*(Nij[1]+Nji[1]));
    }
    reinterpret_cast<float4*>(g_wpack)[d*NENT + entry] = r;
}

// ---------------- stage 1: embeddings e[i][d][b] --------------------------------
__global__ void compute_e(const int* __restrict__ idx,
                          const float* __restrict__ emb_mean,
                          const float* __restrict__ v) {
    int i = blockIdx.y;
    int b = blockIdx.x * 128 + threadIdx.x;
    int idxv = idx[i*BB + b];
    const float* mrow = emb_mean + (i*NE + idxv)*DD;
    const float* srow = g_sp    + (i*NE + idxv)*DD;
    const float* vrow = v + b*DD;
    #pragma unroll 8
    for (int d = 0; d < DD; d++) {
        g_e[(i*DD + d)*BB + b] = fmaf(srow[d], vrow[d], mrow[d]);
    }
}

// ---------------- stage 2: main pairwise kernel ----------------------------------
__global__ void __launch_bounds__(128)
main_kernel() {
    int d = blockIdx.y;
    int b = blockIdx.x * 128 + threadIdx.x;

    __shared__ float4 sw[NENT];
    const float4* wp = reinterpret_cast<const float4*>(g_wpack) + d*NENT;
    for (int t = threadIdx.x; t < NENT; t += 128) sw[t] = wp[t];
    __syncthreads();

    float e[NC];
    #pragma unroll
    for (int i = 0; i < NC; i++) e[i] = g_e[(i*DD + d)*BB + b];

    float a0 = 0.f, a1 = 0.f;

    // linear + diagonal (e_i^2) terms
    #pragma unroll
    for (int i = 0; i < NC; i++) {
        float4 w = sw[i];
        float p = e[i]*e[i];
        a0 += e[i]*w.x + p*w.z;
        a1 += e[i]*w.y + p*w.w;
    }

    // strict-upper pairs: product + |diff| terms
    int pi = NC;
    #pragma unroll
    for (int i = 0; i < NC - 1; i++) {
        #pragma unroll
        for (int j = i + 1; j < NC; j++) {
            float4 w = sw[pi++];
            float p  = e[i]*e[j];
            float ad = fabsf(e[i] - e[j]);
            a0 += p*w.x + ad*w.z;
            a1 += p*w.y + ad*w.w;
        }
    }

    reinterpret_cast<float2*>(g_partial)[d*BB + b] = make_float2(a0, a1);
}

// ---------------- stage 3: reduce over d -----------------------------------------
__global__ void reduce_kernel(float* __restrict__ out) {
    int t = blockIdx.x * 256 + threadIdx.x;   // 0..4095 -> (b,k)
    float s = 0.f;
    #pragma unroll
    for (int d = 0; d < DD; d++) s += g_partial[d*BB*2 + t];
    out[t] = s;
}

// ---------------- launch ----------------------------------------------------------
extern "C" void kernel_launch(void* const* d_in, const int* in_sizes, int n_in,
                              void* d_out, int out_size) {
    const int*   idx       = (const int*)  d_in[0];
    const float* emb_mean  = (const float*)d_in[1];
    const float* emb_std   = (const float*)d_in[2];
    const float* v         = (const float*)d_in[3];
    const float* W_ops     = (const float*)d_in[4];
    const float* W_cat     = (const float*)d_in[5];
    const float* log_alpha = (const float*)d_in[6];
    float* out = (float*)d_out;

    prep_sp<<<(NC*NE*DD + 255)/256, 256>>>(emb_std);
    prep_weights<<<64, dim3(64, 4)>>>(W_ops, W_cat, log_alpha);
    compute_e<<<dim3(BB/128, NC), 128>>>(idx, emb_mean, v);
    main_kernel<<<dim3(BB/128, DD), 128>>>();
    reduce_kernel<<<(BB*2 + 255)/256, 256>>>(out);
}

// round 2
// speedup vs baseline: 1.4745x; 1.4745x over previous
#include <cuda_runtime.h>
#include <math.h>

// Problem constants
#define NC    22            // columns
#define NE    12            // embeddings per column
#define DD    64            // feature dim
#define BB    2048          // batch
#define NPAIR 231           // 22 choose 2
#define NENT  253           // 22 lin/diag entries + 231 pair entries
#define TBL   (NC*NE)       // 264 table rows per d-slice

typedef unsigned long long ull;

// ---------------- device scratch ----------------
__device__ float g_sp[NC * NE * DD];        // 0.01 * softplus(emb_std)
__device__ float g_w[DD * NENT * 8];        // per-d, per-entry lane-duplicated weights
__device__ float g_partial[DD * BB * 2];    // partial[d][b*2+k]

// ---------------- f32x2 packed helpers (sm_100a+) ----------------
__device__ __forceinline__ ull pack2(float lo, float hi) {
    ull r; asm("mov.b64 %0, {%1, %2};" : "=l"(r) : "f"(lo), "f"(hi)); return r;
}
__device__ __forceinline__ void unpack2(ull x, float& lo, float& hi) {
    asm("mov.b64 {%0, %1}, %2;" : "=f"(lo), "=f"(hi) : "l"(x));
}
__device__ __forceinline__ ull fma2(ull a, ull b, ull c) {
    ull r; asm("fma.rn.f32x2 %0, %1, %2, %3;" : "=l"(r) : "l"(a), "l"(b), "l"(c)); return r;
}
__device__ __forceinline__ ull mul2(ull a, ull b) {
    ull r; asm("mul.rn.f32x2 %0, %1, %2;" : "=l"(r) : "l"(a), "l"(b)); return r;
}

// ---------------- stage 0: fused prep (weights + softplus table) -----------------
// blocks [0, NENT): entry workers, 64 threads = d
// blocks [NENT, NENT+264): softplus workers, 64 elements each
__global__ void __launch_bounds__(64)
prep_kernel(const float* __restrict__ W_ops, const float* __restrict__ W_cat,
            const float* __restrict__ log_alpha, const float* __restrict__ emb_std) {
    if (blockIdx.x >= NENT) {
        int t = (blockIdx.x - NENT) * 64 + threadIdx.x;
        if (t < NC * NE * DD) {
            float x = emb_std[t];
            float sp = fmaxf(x, 0.0f) + log1pf(expf(-fabsf(x)));
            g_sp[t] = 0.01f * sp;
        }
        return;
    }
    int entry = blockIdx.x;
    int d = threadIdx.x;

    // softmax over 5 primitives
    float la[5], w[5];
    float mx = -1e30f, s = 0.f;
    #pragma unroll
    for (int z = 0; z < 5; z++) { la[z] = log_alpha[z]; mx = fmaxf(mx, la[z]); }
    #pragma unroll
    for (int z = 0; z < 5; z++) { w[z] = expf(la[z] - mx); s += w[z]; }
    #pragma unroll
    for (int z = 0; z < 5; z++) w[z] /= s;
    float w0 = w[0], w1 = w[1], w2 = w[2], w3 = w[3], w4 = w[4];

    float wx, wy, wz, ww;
    if (entry < NC) {
        int i = entry;
        float l0 = 0.f, l1 = 0.f;
        for (int j = 0; j < NC; j++) {
            const float* Pij = W_ops + (((i*NC+j)*4 + 0)*DD + d)*2;
            const float* Pji = W_ops + (((j*NC+i)*4 + 0)*DD + d)*2;
            const float* Xij = W_ops + (((i*NC+j)*4 + 2)*DD + d)*2;
            const float* Xji = W_ops + (((j*NC+i)*4 + 2)*DD + d)*2;
            const float* Nij = W_ops + (((i*NC+j)*4 + 3)*DD + d)*2;
            const float* Nji = W_ops + (((j*NC+i)*4 + 3)*DD + d)*2;
            const float* Cij  = W_cat + ((i*NC+j)*2*DD + d)*2;        // p half, r = d
            const float* Cjiq = W_cat + ((j*NC+i)*2*DD + DD + d)*2;   // q half, r = 64+d
            l0 += w0*(Pij[0]+Pji[0]) + 0.5f*w2*(Xij[0]+Xji[0])
                + 0.5f*w3*(Nij[0]+Nji[0]) + w4*(Cij[0]+Cjiq[0]);
            l1 += w0*(Pij[1]+Pji[1]) + 0.5f*w2*(Xij[1]+Xji[1])
                + 0.5f*w3*(Nij[1]+Nji[1]) + w4*(Cij[1]+Cjiq[1]);
        }
        const float* Mii = W_ops + (((i*NC+i)*4 + 1)*DD + d)*2;
        wx = l0; wy = l1; wz = w1*Mii[0]; ww = w1*Mii[1];
    } else {
        int p = entry - NC;
        int i = 0, rem = p;
        while (rem >= 21 - i) { rem -= 21 - i; i++; }
        int j = i + 1 + rem;
        const float* Mij = W_ops + (((i*NC+j)*4 + 1)*DD + d)*2;
        const float* Mji = W_ops + (((j*NC+i)*4 + 1)*DD + d)*2;
        const float* Xij = W_ops + (((i*NC+j)*4 + 2)*DD + d)*2;
        const float* Xji = W_ops + (((j*NC+i)*4 + 2)*DD + d)*2;
        const float* Nij = W_ops + (((i*NC+j)*4 + 3)*DD + d)*2;
        const float* Nji = W_ops + (((j*NC+i)*4 + 3)*DD + d)*2;
        wx = w1*(Mij[0]+Mji[0]);
        wy = w1*(Mij[1]+Mji[1]);
        wz = 0.5f*(w2*(Xij[0]+Xji[0]) - w3*(Nij[0]+Nji[0]));
        ww = 0.5f*(w2*(Xij[1]+Xji[1]) - w3*(Nij[1]+Nji[1]));
    }
    // lane-duplicated layout: {wx,wx, wy,wy, wz,wz, ww,ww}
    float4* dst = reinterpret_cast<float4*>(g_w + (d*NENT + entry)*8);
    dst[0] = make_float4(wx, wx, wy, wy);
    dst[1] = make_float4(wz, wz, ww, ww);
}

// ---------------- stage 1: fused main kernel -------------------------------------
// grid: (BB/128) x DD, 64 threads; each thread handles b = b0+tid and b0+tid+64,
// packed in f32x2 lanes.
__global__ void __launch_bounds__(64)
main_kernel(const int* __restrict__ idx, const float* __restrict__ emb_mean,
            const float* __restrict__ v) {
    const int d  = blockIdx.y;
    const int b0 = blockIdx.x * 128;
    const int tid = threadIdx.x;

    __shared__ float swt[NENT * 8];     // 8096 B duplicated weights
    __shared__ float mean_s[TBL];       // per-d embedding-mean slice
    __shared__ float sp_s[TBL];         // per-d softplus slice

    {
        const float4* wp = reinterpret_cast<const float4*>(g_w + d * NENT * 8);
        float4* s4 = reinterpret_cast<float4*>(swt);
        #pragma unroll 4
        for (int t = tid; t < NENT * 2; t += 64) s4[t] = wp[t];
        for (int t = tid; t < TBL; t += 64) {
            mean_s[t] = emb_mean[t * DD + d];
            sp_s[t]   = g_sp[t * DD + d];
        }
    }
    __syncthreads();

    const int b  = b0 + tid;
    const int b2 = b + 64;
    const float vlo = v[b  * DD + d];
    const float vhi = v[b2 * DD + d];

    // embeddings for both b's, packed
    ull e2[NC];
    #pragma unroll
    for (int i = 0; i < NC; i++) {
        int iv  = idx[i * BB + b];
        int iv2 = idx[i * BB + b2];
        float elo = fmaf(sp_s[i * NE + iv],  vlo, mean_s[i * NE + iv]);
        float ehi = fmaf(sp_s[i * NE + iv2], vhi, mean_s[i * NE + iv2]);
        e2[i] = pack2(elo, ehi);
    }

    ull A0 = 0ULL, A1 = 0ULL;
    const ulonglong2* sw2 = reinterpret_cast<const ulonglong2*>(swt);

    // linear + diagonal (e_i^2) terms
    #pragma unroll
    for (int i = 0; i < NC; i++) {
        ulonglong2 wl = sw2[i * 2 + 0];   // {L0,L0},{L1,L1}
        ulonglong2 wd = sw2[i * 2 + 1];   // {D0,D0},{D1,D1}
        ull p2 = mul2(e2[i], e2[i]);
        A0 = fma2(e2[i], wl.x, A0);
        A1 = fma2(e2[i], wl.y, A1);
        A0 = fma2(p2,    wd.x, A0);
        A1 = fma2(p2,    wd.y, A1);
    }

    // strict-upper pairs: product + |diff| terms
    const ull NEG1 = 0xBF800000BF800000ULL;   // {-1.f, -1.f}
    int pi = NC;
    #pragma unroll
    for (int i = 0; i < NC - 1; i++) {
        #pragma unroll
        for (int j = i + 1; j < NC; j++) {
            ulonglong2 wm = sw2[pi * 2 + 0];  // {wm0,wm0},{wm1,wm1}
            ulonglong2 wa = sw2[pi * 2 + 1];  // {wa0,wa0},{wa1,wa1}
            pi++;
            ull p2 = mul2(e2[i], e2[j]);
            ull df = fma2(e2[j], NEG1, e2[i]);
            ull ad = df & 0x7FFFFFFF7FFFFFFFULL;
            A0 = fma2(p2, wm.x, A0);
            A1 = fma2(p2, wm.y, A1);
            A0 = fma2(ad, wa.x, A0);
            A1 = fma2(ad, wa.y, A1);
        }
    }

    float a0l, a0h, a1l, a1h;
    unpack2(A0, a0l, a0h);
    unpack2(A1, a1l, a1h);
    float2* P = reinterpret_cast<float2*>(g_partial);
    P[d * BB + b]  = make_float2(a0l, a1l);
    P[d * BB + b2] = make_float2(a0h, a1h);
}

// ---------------- stage 2: reduce over d -----------------------------------------
__global__ void reduce_kernel(float* __restrict__ out) {
    int t = blockIdx.x * 256 + threadIdx.x;   // 0..4095 -> (b,k)
    float s = 0.f;
    #pragma unroll
    for (int d = 0; d < DD; d++) s += g_partial[d * BB * 2 + t];
    out[t] = s;
}

// ---------------- launch ----------------------------------------------------------
extern "C" void kernel_launch(void* const* d_in, const int* in_sizes, int n_in,
                              void* d_out, int out_size) {
    const int*   idx       = (const int*)  d_in[0];
    const float* emb_mean  = (const float*)d_in[1];
    const float* emb_std   = (const float*)d_in[2];
    const float* v         = (const float*)d_in[3];
    const float* W_ops     = (const float*)d_in[4];
    const float* W_cat     = (const float*)d_in[5];
    const float* log_alpha = (const float*)d_in[6];
    float* out = (float*)d_out;

    const int SP_BLOCKS = (NC * NE * DD + 63) / 64;   // 264
    prep_kernel<<<NENT + SP_BLOCKS, 64>>>(W_ops, W_cat, log_alpha, emb_std);
    main_kernel<<<dim3(BB / 128, DD), 64>>>(idx, emb_mean, v);
    reduce_kernel<<<(BB * 2 + 255) / 256, 256>>>(out);
}

// round 3
// speedup vs baseline: 2.1499x; 1.4580x over previous
#include <cuda_runtime.h>
#include <math.h>

// Problem constants
#define NC    22            // columns
#define NE    12            // embeddings per column
#define DD    64            // feature dim
#define BB    2048          // batch
#define NPAIR 231           // 22 choose 2
#define NENT  253           // 22 lin/diag entries + 231 pair entries
#define TBL   (NC*NE)       // 264 table rows per d-slice

typedef unsigned long long ull;

// ---------------- device scratch ----------------
__device__ float g_sp[NC * NE * DD];        // 0.01 * softplus(emb_std)
__device__ float g_w[DD * NENT * 8];        // per-d, per-entry lane-duplicated weights
__device__ float2 g_c[NC * NC * DD];        // linear contribution of ordered (i,j) at d
__device__ float g_partial[DD * BB * 2];    // partial[d][b*2+k]

// ---------------- f32x2 packed helpers (sm_100a+) ----------------
__device__ __forceinline__ ull pack2(float lo, float hi) {
    ull r; asm("mov.b64 %0, {%1, %2};" : "=l"(r) : "f"(lo), "f"(hi)); return r;
}
__device__ __forceinline__ void unpack2(ull x, float& lo, float& hi) {
    asm("mov.b64 {%0, %1}, %2;" : "=f"(lo), "=f"(hi) : "l"(x));
}
__device__ __forceinline__ ull fma2(ull a, ull b, ull c) {
    ull r; asm("fma.rn.f32x2 %0, %1, %2, %3;" : "=l"(r) : "l"(a), "l"(b), "l"(c)); return r;
}
__device__ __forceinline__ ull mul2(ull a, ull b) {
    ull r; asm("mul.rn.f32x2 %0, %1, %2;" : "=l"(r) : "l"(a), "l"(b)); return r;
}

__device__ __forceinline__ void softmax5(const float* __restrict__ log_alpha, float* w) {
    float la[5];
    float mx = -1e30f, s = 0.f;
    #pragma unroll
    for (int z = 0; z < 5; z++) { la[z] = __ldg(log_alpha + z); mx = fmaxf(mx, la[z]); }
    #pragma unroll
    for (int z = 0; z < 5; z++) { w[z] = expf(la[z] - mx); s += w[z]; }
    float inv = 1.0f / s;
    #pragma unroll
    for (int z = 0; z < 5; z++) w[z] *= inv;
}

// ---------------- stage A: per-(i,j,d) contributions + pair weights + softplus ----
// blocks [0, 121): (i,j,d) workers, 256 threads; 121*256 = 484*64 exactly
// blocks [121, 121+66): softplus workers
#define A_BLOCKS 121
#define SP_BLOCKS ((NC*NE*DD + 255) / 256)   // 66

__global__ void __launch_bounds__(256)
prep_a(const float* __restrict__ W_ops, const float* __restrict__ W_cat,
       const float* __restrict__ log_alpha, const float* __restrict__ emb_std) {
    if (blockIdx.x >= A_BLOCKS) {
        int t = (blockIdx.x - A_BLOCKS) * 256 + threadIdx.x;
        if (t < NC * NE * DD) {
            float x = emb_std[t];
            float sp = fmaxf(x, 0.0f) + log1pf(expf(-fabsf(x)));
            g_sp[t] = 0.01f * sp;
        }
        return;
    }
    int t = blockIdx.x * 256 + threadIdx.x;
    int d  = t & 63;
    int ij = t >> 6;
    int i = ij / NC;
    int j = ij - i * NC;

    float w[5];
    softmax5(log_alpha, w);
    const float w0 = w[0], w1 = w[1], w2 = w[2], w3 = w[3], w4 = w[4];

    const float2* W2 = reinterpret_cast<const float2*>(W_ops);
    const float2* C2 = reinterpret_cast<const float2*>(W_cat);

    // coalesced loads: d is the fastest-varying index
    float2 Pij = W2[((i*NC+j)*4 + 0)*DD + d];
    float2 Pji = W2[((j*NC+i)*4 + 0)*DD + d];
    float2 Xij = W2[((i*NC+j)*4 + 2)*DD + d];
    float2 Xji = W2[((j*NC+i)*4 + 2)*DD + d];
    float2 Nij = W2[((i*NC+j)*4 + 3)*DD + d];
    float2 Nji = W2[((j*NC+i)*4 + 3)*DD + d];
    float2 Cp  = C2[(i*NC+j)*(2*DD) + d];        // p half, row d
    float2 Cq  = C2[(j*NC+i)*(2*DD) + DD + d];   // q half, row 64+d

    float c0 = w0*(Pij.x+Pji.x) + 0.5f*w2*(Xij.x+Xji.x)
             + 0.5f*w3*(Nij.x+Nji.x) + w4*(Cp.x+Cq.x);
    float c1 = w0*(Pij.y+Pji.y) + 0.5f*w2*(Xij.y+Xji.y)
             + 0.5f*w3*(Nij.y+Nji.y) + w4*(Cp.y+Cq.y);
    g_c[(i*NC + j)*DD + d] = make_float2(c0, c1);

    if (i == j) {
        float2 Mii = W2[((i*NC+i)*4 + 1)*DD + d];
        float4* dst = reinterpret_cast<float4*>(g_w + (d*NENT + i)*8);
        dst[1] = make_float4(w1*Mii.x, w1*Mii.x, w1*Mii.y, w1*Mii.y);
    } else if (i < j) {
        float2 Mij = W2[((i*NC+j)*4 + 1)*DD + d];
        float2 Mji = W2[((j*NC+i)*4 + 1)*DD + d];
        float wx = w1*(Mij.x+Mji.x);
        float wy = w1*(Mij.y+Mji.y);
        float wz = 0.5f*(w2*(Xij.x+Xji.x) - w3*(Nij.x+Nji.x));
        float ww = 0.5f*(w2*(Xij.y+Xji.y) - w3*(Nij.y+Nji.y));
        int entry = NC + (i*(2*NC - 1 - i))/2 + (j - i - 1);
        float4* dst = reinterpret_cast<float4*>(g_w + (d*NENT + entry)*8);
        dst[0] = make_float4(wx, wx, wy, wy);
        dst[1] = make_float4(wz, wz, ww, ww);
    }
}

// ---------------- stage B: reduce linear contributions over j --------------------
// 1408 threads = 22*64, 11 blocks x 128
__global__ void __launch_bounds__(128)
prep_b() {
    int t = blockIdx.x * 128 + threadIdx.x;   // i*64 + d
    int d = t & 63;
    int i = t >> 6;
    float l0 = 0.f, l1 = 0.f;
    #pragma unroll
    for (int j = 0; j < NC; j++) {
        float2 c = g_c[(i*NC + j)*DD + d];
        l0 += c.x; l1 += c.y;
    }
    float4* dst = reinterpret_cast<float4*>(g_w + (d*NENT + i)*8);
    dst[0] = make_float4(l0, l0, l1, l1);
}

// ---------------- stage 1: fused main kernel -------------------------------------
__global__ void __launch_bounds__(64)
main_kernel(const int* __restrict__ idx, const float* __restrict__ emb_mean,
            const float* __restrict__ v) {
    const int d  = blockIdx.y;
    const int b0 = blockIdx.x * 128;
    const int tid = threadIdx.x;

    __shared__ float swt[NENT * 8];     // duplicated weights
    __shared__ float mean_s[TBL];       // per-d embedding-mean slice
    __shared__ float sp_s[TBL];         // per-d softplus slice

    {
        const float4* wp = reinterpret_cast<const float4*>(g_w + d * NENT * 8);
        float4* s4 = reinterpret_cast<float4*>(swt);
        #pragma unroll 4
        for (int t = tid; t < NENT * 2; t += 64) s4[t] = wp[t];
        for (int t = tid; t < TBL; t += 64) {
            mean_s[t] = emb_mean[t * DD + d];
            sp_s[t]   = g_sp[t * DD + d];
        }
    }
    __syncthreads();

    const int b  = b0 + tid;
    const int b2 = b + 64;
    const float vlo = v[b  * DD + d];
    const float vhi = v[b2 * DD + d];

    ull e2[NC];
    #pragma unroll
    for (int i = 0; i < NC; i++) {
        int iv  = idx[i * BB + b];
        int iv2 = idx[i * BB + b2];
        float elo = fmaf(sp_s[i * NE + iv],  vlo, mean_s[i * NE + iv]);
        float ehi = fmaf(sp_s[i * NE + iv2], vhi, mean_s[i * NE + iv2]);
        e2[i] = pack2(elo, ehi);
    }

    ull A0 = 0ULL, A1 = 0ULL;
    const ulonglong2* sw2 = reinterpret_cast<const ulonglong2*>(swt);

    #pragma unroll
    for (int i = 0; i < NC; i++) {
        ulonglong2 wl = sw2[i * 2 + 0];
        ulonglong2 wd = sw2[i * 2 + 1];
        ull p2 = mul2(e2[i], e2[i]);
        A0 = fma2(e2[i], wl.x, A0);
        A1 = fma2(e2[i], wl.y, A1);
        A0 = fma2(p2,    wd.x, A0);
        A1 = fma2(p2,    wd.y, A1);
    }

    const ull NEG1 = 0xBF800000BF800000ULL;
    int pi = NC;
    #pragma unroll
    for (int i = 0; i < NC - 1; i++) {
        #pragma unroll
        for (int j = i + 1; j < NC; j++) {
            ulonglong2 wm = sw2[pi * 2 + 0];
            ulonglong2 wa = sw2[pi * 2 + 1];
            pi++;
            ull p2 = mul2(e2[i], e2[j]);
            ull df = fma2(e2[j], NEG1, e2[i]);
            ull ad = df & 0x7FFFFFFF7FFFFFFFULL;
            A0 = fma2(p2, wm.x, A0);
            A1 = fma2(p2, wm.y, A1);
            A0 = fma2(ad, wa.x, A0);
            A1 = fma2(ad, wa.y, A1);
        }
    }

    float a0l, a0h, a1l, a1h;
    unpack2(A0, a0l, a0h);
    unpack2(A1, a1l, a1h);
    float2* P = reinterpret_cast<float2*>(g_partial);
    P[d * BB + b]  = make_float2(a0l, a1l);
    P[d * BB + b2] = make_float2(a0h, a1h);
}

// ---------------- stage 2: reduce over d -----------------------------------------
__global__ void reduce_kernel(float* __restrict__ out) {
    int t = blockIdx.x * 256 + threadIdx.x;   // 0..4095 -> (b,k)
    float s = 0.f;
    #pragma unroll
    for (int d = 0; d < DD; d++) s += g_partial[d * BB * 2 + t];
    out[t] = s;
}

// ---------------- launch ----------------------------------------------------------
extern "C" void kernel_launch(void* const* d_in, const int* in_sizes, int n_in,
                              void* d_out, int out_size) {
    const int*   idx       = (const int*)  d_in[0];
    const float* emb_mean  = (const float*)d_in[1];
    const float* emb_std   = (const float*)d_in[2];
    const float* v         = (const float*)d_in[3];
    const float* W_ops     = (const float*)d_in[4];
    const float* W_cat     = (const float*)d_in[5];
    const float* log_alpha = (const float*)d_in[6];
    float* out = (float*)d_out;

    prep_a<<<A_BLOCKS + SP_BLOCKS, 256>>>(W_ops, W_cat, log_alpha, emb_std);
    prep_b<<<11, 128>>>();
    main_kernel<<<dim3(BB / 128, DD), 64>>>(idx, emb_mean, v);
    reduce_kernel<<<(BB * 2 + 255) / 256, 256>>>(out);
}